// round 15
// baseline (speedup 1.0000x reference)
#include <cuda_runtime.h>

#define BATCH 8
#define TSEQ 2048
#define CDIM 768
#define HDIM 64
#define BT_TOTAL (BATCH*TSEQ)
#define NSPLIT 2

// Projected Q, K (natural [b][s][h]) and V (TRANSPOSED [b][h][s]).
// All values already tf32-RNA-rounded; Q pre-scaled by 0.125*log2(e).
__device__ float g_q[BT_TOTAL*HDIM];
__device__ float g_k[BT_TOTAL*HDIM];
__device__ float g_v[BT_TOTAL*HDIM];
// split-K partials
__device__ float g_po[NSPLIT*BT_TOTAL*HDIM];
__device__ float g_pm[NSPLIT*BT_TOTAL];
__device__ float g_pl[NSPLIT*BT_TOTAL];
// W, pre-rounded (Wq pre-scaled), stored as per-chunk swizzled smem images
__device__ float g_wt[3*HDIM*CDIM];

// ---------------------------------------------------------------------------
__device__ __forceinline__ unsigned f2tf(float f) {
    unsigned u;
    asm("cvt.rna.tf32.f32 %0, %1;" : "=r"(u) : "f"(f));
    return u;
}
__device__ __forceinline__ float f2tff(float f) { return __uint_as_float(f2tf(f)); }

__device__ __forceinline__ void mma_tf32(float c[4],
                                         unsigned a0, unsigned a1, unsigned a2, unsigned a3,
                                         unsigned b0, unsigned b1) {
    asm volatile(
        "mma.sync.aligned.m16n8k8.row.col.f32.tf32.tf32.f32 "
        "{%0,%1,%2,%3},{%4,%5,%6,%7},{%8,%9},{%0,%1,%2,%3};"
        : "+f"(c[0]), "+f"(c[1]), "+f"(c[2]), "+f"(c[3])
        : "r"(a0), "r"(a1), "r"(a2), "r"(a3), "r"(b0), "r"(b1));
}

__device__ __forceinline__ void ldsm4(unsigned &r0, unsigned &r1, unsigned &r2, unsigned &r3,
                                      const float* p) {
    unsigned a = (unsigned)__cvta_generic_to_shared(p);
    asm volatile("ldmatrix.sync.aligned.m8n8.x4.shared.b16 {%0,%1,%2,%3}, [%4];"
                 : "=r"(r0), "=r"(r1), "=r"(r2), "=r"(r3) : "r"(a));
}

__device__ __forceinline__ void cpasync16(float* dst, const float* src) {
    unsigned a = (unsigned)__cvta_generic_to_shared(dst);
    asm volatile("cp.async.cg.shared.global [%0], [%1], 16;" :: "r"(a), "l"(src));
}
#define CP_COMMIT() asm volatile("cp.async.commit_group;")
template<int N> __device__ __forceinline__ void cp_wait() {
    asm volatile("cp.async.wait_group %0;" :: "n"(N));
}

// ---------------------------------------------------------------------------
// Kernel 0: W prep (unchanged).
// ---------------------------------------------------------------------------
__global__ __launch_bounds__(256) void w_prep(const float* __restrict__ Wq,
                                              const float* __restrict__ Wk,
                                              const float* __restrict__ Wv)
{
    int idx = blockIdx.x * 256 + threadIdx.x;        // over 768*192
    int k = idx / 192;
    int n = idx - k * 192;
    const float* W = (n < 64) ? Wq : (n < 128) ? Wk : Wv;
    float v = W[(size_t)k * HDIM + (n & 63)];
    if (n < 64) v *= 0.18033688011112042f;           // 0.125 * log2(e)
    int chunk = k >> 5;
    int kin = k & 31;
    int kg = kin >> 2, rem = kin & 3;
    g_wt[chunk * 6144 + n * 32 + ((kg * 4) ^ ((n & 7) << 2)) + rem] = f2tff(v);
}

// ---------------------------------------------------------------------------
// Kernel 1: FUSED QKV projection (unchanged from R13 pass).
// ---------------------------------------------------------------------------
#define XP 36
#define XS_F (64 * XP)
#define WS_F (192 * 32)

__global__ __launch_bounds__(256, 2) void qkv_proj(const float* __restrict__ x)
{
    extern __shared__ float psm[];
    float* Xst[2] = { psm, psm + XS_F };
    float* Wst[3] = { psm + 2*XS_F, psm + 2*XS_F + WS_F, psm + 2*XS_F + 2*WS_F };

    const int tid  = threadIdx.x;
    const int w    = tid >> 5;
    const int lane = tid & 31;
    const int wq   = w & 1;
    const int wn   = w >> 1;
    const int mw   = wq * 32;
    const int lrow = lane & 7;

    const int idxA = ((((lane >> 3) & 1) * 8 + lrow)) * XP + ((lane >> 4) & 1) * 4;
    const int nr   = ((lane >> 4) & 1) * 8 + lrow;
    const int kb   = ((lane >> 3) & 1) * 4;
    const int xrs  = lrow << 2;

    const size_t m0 = (size_t)blockIdx.x * 64;

    const int xr0 = tid >> 3,         xc0 = (tid & 7) * 4;
    const int xr1 = (tid + 256) >> 3, xc1 = (tid & 7) * 4;
    const int woff = tid * 4;

    float4 xg[2];

    auto ldg_x = [&](int kc) {
        xg[0] = *(const float4*)(x + (m0 + xr0) * CDIM + kc + xc0);
        xg[1] = *(const float4*)(x + (m0 + xr1) * CDIM + kc + xc1);
    };
    auto sts_x = [&](int s) {
        float4 v0 = xg[0], v1 = xg[1];
        v0.x = f2tff(v0.x); v0.y = f2tff(v0.y); v0.z = f2tff(v0.z); v0.w = f2tff(v0.w);
        v1.x = f2tff(v1.x); v1.y = f2tff(v1.y); v1.z = f2tff(v1.z); v1.w = f2tff(v1.w);
        *(float4*)&Xst[s][xr0 * XP + xc0] = v0;
        *(float4*)&Xst[s][xr1 * XP + xc1] = v1;
    };
    auto cp_w = [&](int ch, int s) {
        const float* src = g_wt + ch * WS_F + woff;
        float* dst = Wst[s] + woff;
        #pragma unroll
        for (int rep = 0; rep < 6; rep++)
            cpasync16(dst + rep * 1024, src + rep * 1024);
    };

    float acc[2][6][4];
    #pragma unroll
    for (int im = 0; im < 2; im++)
        #pragma unroll
        for (int j = 0; j < 6; j++)
            #pragma unroll
            for (int c = 0; c < 4; c++) acc[im][j][c] = 0.0f;

    cp_w(0, 0); CP_COMMIT();
    cp_w(1, 1); CP_COMMIT();
    ldg_x(0);
    sts_x(0);

    const int NCH = CDIM / 32;   // 24
    for (int ch = 0; ch < NCH; ch++) {
        const int sx = ch & 1;
        const int sw = ch % 3;
        if (ch + 1 < NCH) ldg_x((ch + 1) * 32);

        cp_wait<1>();
        __syncthreads();

        if (ch + 2 < NCH) cp_w(ch + 2, (ch + 2) % 3);
        CP_COMMIT();

        const float* Xs = Xst[sx];
        const float* Ws = Wst[sw];

        #pragma unroll
        for (int ks = 0; ks < 4; ks++) {
            const int kk = ks * 8;
            unsigned a00, a01, a02, a03, a10, a11, a12, a13;
            ldsm4(a00, a01, a02, a03, Xs + (mw)      * XP + kk + idxA);
            ldsm4(a10, a11, a12, a13, Xs + (mw + 16) * XP + kk + idxA);
            const int koff = (kk + kb) ^ xrs;
            #pragma unroll
            for (int j0 = 0; j0 < 6; j0 += 2) {
                unsigned b00, b10, b01, b11;
                ldsm4(b00, b10, b01, b11,
                      Ws + (wn * 48 + j0 * 8 + nr) * 32 + koff);
                mma_tf32(acc[0][j0],     a00, a01, a02, a03, b00, b10);
                mma_tf32(acc[0][j0 + 1], a00, a01, a02, a03, b01, b11);
                mma_tf32(acc[1][j0],     a10, a11, a12, a13, b00, b10);
                mma_tf32(acc[1][j0 + 1], a10, a11, a12, a13, b01, b11);
            }
        }
        if (ch + 1 < NCH) sts_x(sx ^ 1);
    }

    const int g = lane >> 2, t = lane & 3;
    const int bb = (int)(m0 >> 11);

    #pragma unroll
    for (int im = 0; im < 2; im++) {
        const size_t rb = m0 + mw + im * 16 + g;
        const int s0 = ((int)m0 & 2047) + mw + im * 16 + g;
        #pragma unroll
        for (int j = 0; j < 6; j++) {
            int n   = wn * 48 + j * 8;
            int mat = n >> 6;
            int col = (n & 63) + 2 * t;
            if (mat == 0) {
                *(float2*)(g_q + rb       * HDIM + col) =
                    make_float2(f2tff(acc[im][j][0]), f2tff(acc[im][j][1]));
                *(float2*)(g_q + (rb + 8) * HDIM + col) =
                    make_float2(f2tff(acc[im][j][2]), f2tff(acc[im][j][3]));
            } else if (mat == 1) {
                *(float2*)(g_k + rb       * HDIM + col) =
                    make_float2(f2tff(acc[im][j][0]), f2tff(acc[im][j][1]));
                *(float2*)(g_k + (rb + 8) * HDIM + col) =
                    make_float2(f2tff(acc[im][j][2]), f2tff(acc[im][j][3]));
            } else {
                g_v[((size_t)bb * 64 + col)     * TSEQ + s0]     = f2tff(acc[im][j][0]);
                g_v[((size_t)bb * 64 + col + 1) * TSEQ + s0]     = f2tff(acc[im][j][1]);
                g_v[((size_t)bb * 64 + col)     * TSEQ + s0 + 8] = f2tff(acc[im][j][2]);
                g_v[((size_t)bb * 64 + col + 1) * TSEQ + s0 + 8] = f2tff(acc[im][j][3]);
            }
        }
    }
}

// ---------------------------------------------------------------------------
// Kernel 2: split-K flash attention, q-tile 128, 4 warps x m32.
// smem (112KB): K double-buffered (2x16KB) + V (16KB) + Q (32KB) + P (32KB).
// 2 CTAs/SM. Grid (32, 8): blockIdx.x -> (qt in 0..15, split in 0..1);
// each split processes exactly qt+1 kv tiles (never empty).
// ---------------------------------------------------------------------------
#define ATF 4096   // floats per 64x64 tile
#define QTF 8192   // floats per 128x64 tile

__global__ __launch_bounds__(128, 2) void attn_part(int dummy)
{
    extern __shared__ float sm[];
    float* Vs = sm + 2 * ATF;
    float* Qs = sm + 3 * ATF;
    float* Ps = Qs + QTF;

    const int tid  = threadIdx.x;
    const int w    = tid >> 5;
    const int lane = tid & 31;
    const int g    = lane >> 2;
    const int t    = lane & 3;
    const int b    = blockIdx.y;
    const int qt    = 15 - (blockIdx.x >> 1);     // heavy q-tiles first
    const int split = blockIdx.x & 1;
    const int mw   = w * 32;
    const int lrow = lane & 7;

    const int kt0 = split ? (qt + 1) : 0;
    const int kt1 = split ? (2 * qt + 2) : (qt + 1);

    const size_t rbase = (size_t)split * BT_TOTAL + (size_t)b * TSEQ + qt * 128;

    const int arA = ((lane >> 3) & 1) * 8 + lrow;
    const int kaA = ((lane >> 4) & 1) * 4;
    const int nrB = ((lane >> 4) & 1) * 8 + lrow;
    const int kbB = ((lane >> 3) & 1) * 4;
    const int xsw = lrow << 2;

    const float* kb = g_k + (size_t)b * TSEQ * HDIM;   // [s][h]
    const float* vb = g_v + (size_t)b * HDIM * TSEQ;   // [h][s]

    auto ld_tile = [&](float* dst, const float* src, int pitch) {
        #pragma unroll
        for (int rep = 0; rep < 8; rep++) {
            int e = tid + rep * 128;
            int r = e >> 4, c4 = (e & 15) * 4;
            cpasync16(&dst[r * 64 + (c4 ^ ((r & 7) << 2))], src + r * pitch + c4);
        }
    };

    // prologue: Q (128 rows), K(kt0), V(kt0)
    {
        const float* qb = g_q + ((size_t)b * TSEQ + qt * 128) * HDIM;
        #pragma unroll
        for (int rep = 0; rep < 16; rep++) {
            int e = tid + rep * 128;
            int r = e >> 4, c4 = (e & 15) * 4;
            cpasync16(&Qs[r * 64 + (c4 ^ ((r & 7) << 2))], qb + r * HDIM + c4);
        }
    }
    CP_COMMIT();
    ld_tile(sm, kb + (size_t)kt0 * 64 * HDIM, HDIM);
    CP_COMMIT();
    ld_tile(Vs, vb + kt0 * 64, TSEQ);
    CP_COMMIT();

    float m_i[2][2] = {{-1e30f, -1e30f}, {-1e30f, -1e30f}};
    float l_i[2][2] = {{0.0f, 0.0f}, {0.0f, 0.0f}};
    float o[2][8][4];
    #pragma unroll
    for (int im = 0; im < 2; im++)
        #pragma unroll
        for (int j = 0; j < 8; j++)
            #pragma unroll
            for (int c = 0; c < 4; c++) o[im][j][c] = 0.0f;

    const int niter = kt1 - kt0;
    for (int i = 0; i < niter; i++) {
        const int kt = kt0 + i;
        const int s  = i & 1;
        if (i + 1 < niter)
            ld_tile(sm + (s ^ 1) * ATF, kb + (size_t)(kt + 1) * 64 * HDIM, HDIM);
        CP_COMMIT();
        cp_wait<2>();        // Q (iter 0) and K(kt) resident
        __syncthreads();

        const float* Ks = sm + s * ATF;

        // ---- S = Q K^T (m32 x n64) ----
        float sc[2][8][4];
        #pragma unroll
        for (int im = 0; im < 2; im++)
            #pragma unroll
            for (int j = 0; j < 8; j++)
                #pragma unroll
                for (int c = 0; c < 4; c++) sc[im][j][c] = 0.0f;

        #pragma unroll
        for (int ks = 0; ks < 8; ks++) {
            const int kk = ks * 8;
            unsigned a00, a01, a02, a03, a10, a11, a12, a13;
            ldsm4(a00, a01, a02, a03, Qs + (mw + arA)      * 64 + ((kk + kaA) ^ xsw));
            ldsm4(a10, a11, a12, a13, Qs + (mw + 16 + arA) * 64 + ((kk + kaA) ^ xsw));
            const int koff = (kk + kbB) ^ xsw;
            #pragma unroll
            for (int j0 = 0; j0 < 8; j0 += 2) {
                unsigned b00, b10, b01, b11;
                ldsm4(b00, b10, b01, b11, Ks + (j0 * 8 + nrB) * 64 + koff);
                mma_tf32(sc[0][j0],     a00, a01, a02, a03, b00, b10);
                mma_tf32(sc[0][j0 + 1], a00, a01, a02, a03, b01, b11);
                mma_tf32(sc[1][j0],     a10, a11, a12, a13, b00, b10);
                mma_tf32(sc[1][j0 + 1], a10, a11, a12, a13, b01, b11);
            }
        }

        // ---- causal mask (last two kv tiles of this q-tile) ----
        if (kt >= 2 * qt) {
            const int doff = (kt - 2 * qt) * 64;
            #pragma unroll
            for (int im = 0; im < 2; im++)
                #pragma unroll
                for (int j = 0; j < 8; j++)
                    #pragma unroll
                    for (int c = 0; c < 4; c++) {
                        int col = doff + j * 8 + 2 * t + (c & 1);
                        int row = mw + im * 16 + g + ((c >> 1) << 3);
                        if (col > row) sc[im][j][c] = -1e30f;
                    }
        }

        // ---- online softmax (exp2 domain) ----
        #pragma unroll
        for (int im = 0; im < 2; im++) {
            #pragma unroll
            for (int h = 0; h < 2; h++) {
                const int c0 = h * 2, c1 = h * 2 + 1;
                float mx = -1e30f;
                #pragma unroll
                for (int j = 0; j < 8; j++)
                    mx = fmaxf(mx, fmaxf(sc[im][j][c0], sc[im][j][c1]));
                mx = fmaxf(mx, __shfl_xor_sync(0xffffffffu, mx, 1));
                mx = fmaxf(mx, __shfl_xor_sync(0xffffffffu, mx, 2));
                float mnew = fmaxf(m_i[im][h], mx);
                float alpha = exp2f(m_i[im][h] - mnew);
                float rs = 0.0f;
                #pragma unroll
                for (int j = 0; j < 8; j++) {
                    sc[im][j][c0] = exp2f(sc[im][j][c0] - mnew);
                    sc[im][j][c1] = exp2f(sc[im][j][c1] - mnew);
                    rs += sc[im][j][c0] + sc[im][j][c1];
                }
                rs += __shfl_xor_sync(0xffffffffu, rs, 1);
                rs += __shfl_xor_sync(0xffffffffu, rs, 2);
                l_i[im][h] = l_i[im][h] * alpha + rs;
                m_i[im][h] = mnew;
                #pragma unroll
                for (int j = 0; j < 8; j++) {
                    o[im][j][c0] *= alpha;
                    o[im][j][c1] *= alpha;
                }
            }
        }

        // ---- stage P (tf32-rounded) into this warp's rows of Ps ----
        #pragma unroll
        for (int im = 0; im < 2; im++) {
            const int r0 = mw + im * 16 + g;
            #pragma unroll
            for (int j = 0; j < 8; j++) {
                const int c   = j * 8 + 2 * t;
                const int cb  = c & ~3;
                const int rem = c & 3;
                *(float2*)&Ps[r0       * 64 + (cb ^ (g << 2)) + rem] =
                    make_float2(f2tff(sc[im][j][0]), f2tff(sc[im][j][1]));
                *(float2*)&Ps[(r0 + 8) * 64 + (cb ^ (g << 2)) + rem] =
                    make_float2(f2tff(sc[im][j][2]), f2tff(sc[im][j][3]));
            }
        }
        __syncwarp();

        cp_wait<1>();       // V(kt) resident
        __syncthreads();

        // ---- O += P V ----
        #pragma unroll
        for (int ks = 0; ks < 8; ks++) {
            const int kk = ks * 8;
            unsigned a00, a01, a02, a03, a10, a11, a12, a13;
            ldsm4(a00, a01, a02, a03, Ps + (mw + arA)      * 64 + ((kk + kaA) ^ xsw));
            ldsm4(a10, a11, a12, a13, Ps + (mw + 16 + arA) * 64 + ((kk + kaA) ^ xsw));
            const int koff = (kk + kbB) ^ xsw;
            #pragma unroll
            for (int j0 = 0; j0 < 8; j0 += 2) {
                unsigned b00, b10, b01, b11;
                ldsm4(b00, b10, b01, b11, Vs + (j0 * 8 + nrB) * 64 + koff);
                mma_tf32(o[0][j0],     a00, a01, a02, a03, b00, b10);
                mma_tf32(o[0][j0 + 1], a00, a01, a02, a03, b01, b11);
                mma_tf32(o[1][j0],     a10, a11, a12, a13, b00, b10);
                mma_tf32(o[1][j0 + 1], a10, a11, a12, a13, b01, b11);
            }
        }
        __syncthreads();    // all warps done reading Vs before overwrite

        if (i + 1 < niter)
            ld_tile(Vs, vb + (kt + 1) * 64, TSEQ);
        CP_COMMIT();
    }

    // ---- store partials (unnormalized O, m, l) ----
    float* po = g_po + rbase * HDIM;
    #pragma unroll
    for (int im = 0; im < 2; im++) {
        const int r0 = mw + im * 16 + g;
        #pragma unroll
        for (int j = 0; j < 8; j++) {
            *(float2*)(po + r0       * HDIM + j * 8 + 2 * t) =
                make_float2(o[im][j][0], o[im][j][1]);
            *(float2*)(po + (r0 + 8) * HDIM + j * 8 + 2 * t) =
                make_float2(o[im][j][2], o[im][j][3]);
        }
        if (t == 0) {
            g_pm[rbase + r0]     = m_i[im][0];
            g_pl[rbase + r0]     = l_i[im][0];
            g_pm[rbase + r0 + 8] = m_i[im][1];
            g_pl[rbase + r0 + 8] = l_i[im][1];
        }
    }
}

// ---------------------------------------------------------------------------
// Kernel 3: combine splits (unchanged).
// ---------------------------------------------------------------------------
__global__ __launch_bounds__(256) void attn_combine(float* __restrict__ out)
{
    int idx8 = blockIdx.x * 256 + threadIdx.x;
    int base = idx8 * 8;
    int r = base >> 6;
    float m0 = g_pm[r], m1 = g_pm[BT_TOTAL + r];
    float l0 = g_pl[r], l1 = g_pl[BT_TOTAL + r];
    float4 a0 = *(const float4*)(g_po + base);
    float4 a1 = *(const float4*)(g_po + base + 4);
    float4 c0 = *(const float4*)(g_po + (size_t)BT_TOTAL * HDIM + base);
    float4 c1 = *(const float4*)(g_po + (size_t)BT_TOTAL * HDIM + base + 4);
    float M  = fmaxf(m0, m1);
    float w0 = exp2f(m0 - M), w1 = exp2f(m1 - M);
    float inv = 1.0f / (l0 * w0 + l1 * w1);
    float4 o0, o1;
    o0.x = (a0.x * w0 + c0.x * w1) * inv;
    o0.y = (a0.y * w0 + c0.y * w1) * inv;
    o0.z = (a0.z * w0 + c0.z * w1) * inv;
    o0.w = (a0.w * w0 + c0.w * w1) * inv;
    o1.x = (a1.x * w0 + c1.x * w1) * inv;
    o1.y = (a1.y * w0 + c1.y * w1) * inv;
    o1.z = (a1.z * w0 + c1.z * w1) * inv;
    o1.w = (a1.w * w0 + c1.w * w1) * inv;
    *(float4*)(out + base)     = o0;
    *(float4*)(out + base + 4) = o1;
}

// ---------------------------------------------------------------------------
extern "C" void kernel_launch(void* const* d_in, const int* in_sizes, int n_in,
                              void* d_out, int out_size)
{
    (void)in_sizes; (void)n_in; (void)out_size;
    const float* x  = (const float*)d_in[0];
    const float* Wq = (const float*)d_in[1];
    const float* Wk = (const float*)d_in[2];
    const float* Wv = (const float*)d_in[3];
    float* out = (float*)d_out;

    const int proj_smem = (2 * XS_F + 3 * WS_F) * (int)sizeof(float);  // 92160
    cudaFuncSetAttribute(qkv_proj, cudaFuncAttributeMaxDynamicSharedMemorySize,
                         proj_smem);
    const int attn_smem = (3 * ATF + 2 * QTF) * (int)sizeof(float);    // 114688
    cudaFuncSetAttribute(attn_part, cudaFuncAttributeMaxDynamicSharedMemorySize,
                         attn_smem);

    w_prep<<<(3 * HDIM * CDIM) / 256, 256>>>(Wq, Wk, Wv);

    qkv_proj<<<BT_TOTAL / 64, 256, proj_smem>>>(x);

    dim3 gattn(2 * TSEQ / 128, BATCH);
    attn_part<<<gattn, 128, attn_smem>>>(0);

    attn_combine<<<BT_TOTAL * HDIM / 2048, 256>>>(out);
}

// round 16
// speedup vs baseline: 1.1571x; 1.1571x over previous
#include <cuda_runtime.h>

#define BATCH 8
#define TSEQ 2048
#define CDIM 768
#define HDIM 64
#define BT_TOTAL (BATCH*TSEQ)
#define NSPLIT 4

// Projected Q, K (natural [b][s][h]) and V (TRANSPOSED [b][h][s]).
// All values already tf32-RNA-rounded; Q pre-scaled by 0.125*log2(e).
__device__ float g_q[BT_TOTAL*HDIM];
__device__ float g_k[BT_TOTAL*HDIM];
__device__ float g_v[BT_TOTAL*HDIM];
// split-K partials
__device__ float g_po[NSPLIT*BT_TOTAL*HDIM];
__device__ float g_pm[NSPLIT*BT_TOTAL];
__device__ float g_pl[NSPLIT*BT_TOTAL];
// W, pre-rounded (Wq pre-scaled), stored as per-chunk swizzled smem images
__device__ float g_wt[3*HDIM*CDIM];

// ---------------------------------------------------------------------------
__device__ __forceinline__ unsigned f2tf(float f) {
    unsigned u;
    asm("cvt.rna.tf32.f32 %0, %1;" : "=r"(u) : "f"(f));
    return u;
}
__device__ __forceinline__ float f2tff(float f) { return __uint_as_float(f2tf(f)); }

__device__ __forceinline__ void mma_tf32(float c[4],
                                         unsigned a0, unsigned a1, unsigned a2, unsigned a3,
                                         unsigned b0, unsigned b1) {
    asm volatile(
        "mma.sync.aligned.m16n8k8.row.col.f32.tf32.tf32.f32 "
        "{%0,%1,%2,%3},{%4,%5,%6,%7},{%8,%9},{%0,%1,%2,%3};"
        : "+f"(c[0]), "+f"(c[1]), "+f"(c[2]), "+f"(c[3])
        : "r"(a0), "r"(a1), "r"(a2), "r"(a3), "r"(b0), "r"(b1));
}

__device__ __forceinline__ void ldsm4(unsigned &r0, unsigned &r1, unsigned &r2, unsigned &r3,
                                      const float* p) {
    unsigned a = (unsigned)__cvta_generic_to_shared(p);
    asm volatile("ldmatrix.sync.aligned.m8n8.x4.shared.b16 {%0,%1,%2,%3}, [%4];"
                 : "=r"(r0), "=r"(r1), "=r"(r2), "=r"(r3) : "r"(a));
}

__device__ __forceinline__ void cpasync16(float* dst, const float* src) {
    unsigned a = (unsigned)__cvta_generic_to_shared(dst);
    asm volatile("cp.async.cg.shared.global [%0], [%1], 16;" :: "r"(a), "l"(src));
}
#define CP_COMMIT() asm volatile("cp.async.commit_group;")
template<int N> __device__ __forceinline__ void cp_wait() {
    asm volatile("cp.async.wait_group %0;" :: "n"(N));
}

// ---------------------------------------------------------------------------
// Kernel 0: W prep (unchanged).
// ---------------------------------------------------------------------------
__global__ __launch_bounds__(256) void w_prep(const float* __restrict__ Wq,
                                              const float* __restrict__ Wk,
                                              const float* __restrict__ Wv)
{
    int idx = blockIdx.x * 256 + threadIdx.x;        // over 768*192
    int k = idx / 192;
    int n = idx - k * 192;
    const float* W = (n < 64) ? Wq : (n < 128) ? Wk : Wv;
    float v = W[(size_t)k * HDIM + (n & 63)];
    if (n < 64) v *= 0.18033688011112042f;           // 0.125 * log2(e)
    int chunk = k >> 5;
    int kin = k & 31;
    int kg = kin >> 2, rem = kin & 3;
    g_wt[chunk * 6144 + n * 32 + ((kg * 4) ^ ((n & 7) << 2)) + rem] = f2tff(v);
}

// ---------------------------------------------------------------------------
// Kernel 1: FUSED QKV projection (unchanged from R13 pass).
// ---------------------------------------------------------------------------
#define XP 36
#define XS_F (64 * XP)
#define WS_F (192 * 32)

__global__ __launch_bounds__(256, 2) void qkv_proj(const float* __restrict__ x)
{
    extern __shared__ float psm[];
    float* Xst[2] = { psm, psm + XS_F };
    float* Wst[3] = { psm + 2*XS_F, psm + 2*XS_F + WS_F, psm + 2*XS_F + 2*WS_F };

    const int tid  = threadIdx.x;
    const int w    = tid >> 5;
    const int lane = tid & 31;
    const int wq   = w & 1;
    const int wn   = w >> 1;
    const int mw   = wq * 32;
    const int lrow = lane & 7;

    const int idxA = ((((lane >> 3) & 1) * 8 + lrow)) * XP + ((lane >> 4) & 1) * 4;
    const int nr   = ((lane >> 4) & 1) * 8 + lrow;
    const int kb   = ((lane >> 3) & 1) * 4;
    const int xrs  = lrow << 2;

    const size_t m0 = (size_t)blockIdx.x * 64;

    const int xr0 = tid >> 3,         xc0 = (tid & 7) * 4;
    const int xr1 = (tid + 256) >> 3, xc1 = (tid & 7) * 4;
    const int woff = tid * 4;

    float4 xg[2];

    auto ldg_x = [&](int kc) {
        xg[0] = *(const float4*)(x + (m0 + xr0) * CDIM + kc + xc0);
        xg[1] = *(const float4*)(x + (m0 + xr1) * CDIM + kc + xc1);
    };
    auto sts_x = [&](int s) {
        float4 v0 = xg[0], v1 = xg[1];
        v0.x = f2tff(v0.x); v0.y = f2tff(v0.y); v0.z = f2tff(v0.z); v0.w = f2tff(v0.w);
        v1.x = f2tff(v1.x); v1.y = f2tff(v1.y); v1.z = f2tff(v1.z); v1.w = f2tff(v1.w);
        *(float4*)&Xst[s][xr0 * XP + xc0] = v0;
        *(float4*)&Xst[s][xr1 * XP + xc1] = v1;
    };
    auto cp_w = [&](int ch, int s) {
        const float* src = g_wt + ch * WS_F + woff;
        float* dst = Wst[s] + woff;
        #pragma unroll
        for (int rep = 0; rep < 6; rep++)
            cpasync16(dst + rep * 1024, src + rep * 1024);
    };

    float acc[2][6][4];
    #pragma unroll
    for (int im = 0; im < 2; im++)
        #pragma unroll
        for (int j = 0; j < 6; j++)
            #pragma unroll
            for (int c = 0; c < 4; c++) acc[im][j][c] = 0.0f;

    cp_w(0, 0); CP_COMMIT();
    cp_w(1, 1); CP_COMMIT();
    ldg_x(0);
    sts_x(0);

    const int NCH = CDIM / 32;   // 24
    for (int ch = 0; ch < NCH; ch++) {
        const int sx = ch & 1;
        const int sw = ch % 3;
        if (ch + 1 < NCH) ldg_x((ch + 1) * 32);

        cp_wait<1>();
        __syncthreads();

        if (ch + 2 < NCH) cp_w(ch + 2, (ch + 2) % 3);
        CP_COMMIT();

        const float* Xs = Xst[sx];
        const float* Ws = Wst[sw];

        #pragma unroll
        for (int ks = 0; ks < 4; ks++) {
            const int kk = ks * 8;
            unsigned a00, a01, a02, a03, a10, a11, a12, a13;
            ldsm4(a00, a01, a02, a03, Xs + (mw)      * XP + kk + idxA);
            ldsm4(a10, a11, a12, a13, Xs + (mw + 16) * XP + kk + idxA);
            const int koff = (kk + kb) ^ xrs;
            #pragma unroll
            for (int j0 = 0; j0 < 6; j0 += 2) {
                unsigned b00, b10, b01, b11;
                ldsm4(b00, b10, b01, b11,
                      Ws + (wn * 48 + j0 * 8 + nr) * 32 + koff);
                mma_tf32(acc[0][j0],     a00, a01, a02, a03, b00, b10);
                mma_tf32(acc[0][j0 + 1], a00, a01, a02, a03, b01, b11);
                mma_tf32(acc[1][j0],     a10, a11, a12, a13, b00, b10);
                mma_tf32(acc[1][j0 + 1], a10, a11, a12, a13, b01, b11);
            }
        }
        if (ch + 1 < NCH) sts_x(sx ^ 1);
    }

    const int g = lane >> 2, t = lane & 3;
    const int bb = (int)(m0 >> 11);

    #pragma unroll
    for (int im = 0; im < 2; im++) {
        const size_t rb = m0 + mw + im * 16 + g;
        const int s0 = ((int)m0 & 2047) + mw + im * 16 + g;
        #pragma unroll
        for (int j = 0; j < 6; j++) {
            int n   = wn * 48 + j * 8;
            int mat = n >> 6;
            int col = (n & 63) + 2 * t;
            if (mat == 0) {
                *(float2*)(g_q + rb       * HDIM + col) =
                    make_float2(f2tff(acc[im][j][0]), f2tff(acc[im][j][1]));
                *(float2*)(g_q + (rb + 8) * HDIM + col) =
                    make_float2(f2tff(acc[im][j][2]), f2tff(acc[im][j][3]));
            } else if (mat == 1) {
                *(float2*)(g_k + rb       * HDIM + col) =
                    make_float2(f2tff(acc[im][j][0]), f2tff(acc[im][j][1]));
                *(float2*)(g_k + (rb + 8) * HDIM + col) =
                    make_float2(f2tff(acc[im][j][2]), f2tff(acc[im][j][3]));
            } else {
                g_v[((size_t)bb * 64 + col)     * TSEQ + s0]     = f2tff(acc[im][j][0]);
                g_v[((size_t)bb * 64 + col + 1) * TSEQ + s0]     = f2tff(acc[im][j][1]);
                g_v[((size_t)bb * 64 + col)     * TSEQ + s0 + 8] = f2tff(acc[im][j][2]);
                g_v[((size_t)bb * 64 + col + 1) * TSEQ + s0 + 8] = f2tff(acc[im][j][3]);
            }
        }
    }
}

// ---------------------------------------------------------------------------
// Kernel 2: split-K flash attention partials (R13 body, NSPLIT=4).
// q-tile 64, 4 warps x m16, 64KB smem, 3 CTAs/SM.
// Grid (128, 8): blockIdx.x -> (qt in 0..31, split in 0..3).
// Split s owns kv tiles [s*nkv/4, (s+1)*nkv/4).
// ---------------------------------------------------------------------------
#define ATF 4096   // floats per 64x64 tile

__global__ __launch_bounds__(128, 3) void attn_part(int dummy)
{
    extern __shared__ float sm[];
    float* Vs  = sm + 2 * ATF;
    float* QPs = sm + 3 * ATF;

    const int tid  = threadIdx.x;
    const int w    = tid >> 5;
    const int lane = tid & 31;
    const int g    = lane >> 2;
    const int t    = lane & 3;
    const int b    = blockIdx.y;
    const int qt    = 31 - (blockIdx.x >> 2);     // heavy q-tiles first
    const int split = blockIdx.x & 3;
    const int mw   = w * 16;
    const int lrow = lane & 7;

    const int nkv = qt + 1;
    const int kt0 = (split * nkv) >> 2;
    const int kt1 = ((split + 1) * nkv) >> 2;

    const size_t rbase = (size_t)split * BT_TOTAL + (size_t)b * TSEQ + qt * 64;

    if (kt0 == kt1) {
        for (int e = tid; e < 64 * HDIM; e += 128)
            g_po[(rbase + (e >> 6)) * HDIM + (e & 63)] = 0.0f;
        for (int r = tid; r < 64; r += 128) {
            g_pm[rbase + r] = -1e30f;
            g_pl[rbase + r] = 0.0f;
        }
        return;
    }

    const int arA = ((lane >> 3) & 1) * 8 + lrow;
    const int kaA = ((lane >> 4) & 1) * 4;
    const int nrB = ((lane >> 4) & 1) * 8 + lrow;
    const int kbB = ((lane >> 3) & 1) * 4;
    const int xsw = lrow << 2;

    const float* kb = g_k + (size_t)b * TSEQ * HDIM;
    const float* vb = g_v + (size_t)b * HDIM * TSEQ;

    auto ld_tile = [&](float* dst, const float* src, int pitch) {
        #pragma unroll
        for (int rep = 0; rep < 8; rep++) {
            int e = tid + rep * 128;
            int r = e >> 4, c4 = (e & 15) * 4;
            cpasync16(&dst[r * 64 + (c4 ^ ((r & 7) << 2))], src + r * pitch + c4);
        }
    };

    ld_tile(QPs, g_q + ((size_t)b * TSEQ + qt * 64) * HDIM, HDIM);
    CP_COMMIT();
    ld_tile(sm, kb + (size_t)kt0 * 64 * HDIM, HDIM);
    CP_COMMIT();
    ld_tile(Vs, vb + kt0 * 64, TSEQ);
    CP_COMMIT();
    cp_wait<2>();
    __syncthreads();

    unsigned qa[8][4];
    #pragma unroll
    for (int ks = 0; ks < 8; ks++)
        ldsm4(qa[ks][0], qa[ks][1], qa[ks][2], qa[ks][3],
              QPs + (mw + arA) * 64 + ((ks * 8 + kaA) ^ xsw));

    float m_i[2] = {-1e30f, -1e30f};
    float l_i[2] = {0.0f, 0.0f};
    float o[8][4];
    #pragma unroll
    for (int j = 0; j < 8; j++)
        #pragma unroll
        for (int c = 0; c < 4; c++) o[j][c] = 0.0f;

    const int niter = kt1 - kt0;
    for (int i = 0; i < niter; i++) {
        const int kt = kt0 + i;
        const int s  = i & 1;
        if (i + 1 < niter)
            ld_tile(sm + (s ^ 1) * ATF, kb + (size_t)(kt + 1) * 64 * HDIM, HDIM);
        CP_COMMIT();
        cp_wait<2>();
        __syncthreads();

        const float* Ks = sm + s * ATF;

        float sc[8][4];
        #pragma unroll
        for (int j = 0; j < 8; j++)
            #pragma unroll
            for (int c = 0; c < 4; c++) sc[j][c] = 0.0f;

        #pragma unroll
        for (int ks = 0; ks < 8; ks++) {
            const int koff = (ks * 8 + kbB) ^ xsw;
            #pragma unroll
            for (int j0 = 0; j0 < 8; j0 += 2) {
                unsigned b00, b10, b01, b11;
                ldsm4(b00, b10, b01, b11, Ks + (j0 * 8 + nrB) * 64 + koff);
                mma_tf32(sc[j0],     qa[ks][0], qa[ks][1], qa[ks][2], qa[ks][3], b00, b10);
                mma_tf32(sc[j0 + 1], qa[ks][0], qa[ks][1], qa[ks][2], qa[ks][3], b01, b11);
            }
        }

        if (kt == qt) {
            #pragma unroll
            for (int j = 0; j < 8; j++)
                #pragma unroll
                for (int c = 0; c < 4; c++) {
                    int col = j * 8 + 2 * t + (c & 1);
                    int row = mw + g + ((c >> 1) << 3);
                    if (col > row) sc[j][c] = -1e30f;
                }
        }

        #pragma unroll
        for (int h = 0; h < 2; h++) {
            const int c0 = h * 2, c1 = h * 2 + 1;
            float mx = -1e30f;
            #pragma unroll
            for (int j = 0; j < 8; j++)
                mx = fmaxf(mx, fmaxf(sc[j][c0], sc[j][c1]));
            mx = fmaxf(mx, __shfl_xor_sync(0xffffffffu, mx, 1));
            mx = fmaxf(mx, __shfl_xor_sync(0xffffffffu, mx, 2));
            float mnew = fmaxf(m_i[h], mx);
            float alpha = exp2f(m_i[h] - mnew);
            float rs = 0.0f;
            #pragma unroll
            for (int j = 0; j < 8; j++) {
                sc[j][c0] = exp2f(sc[j][c0] - mnew);
                sc[j][c1] = exp2f(sc[j][c1] - mnew);
                rs += sc[j][c0] + sc[j][c1];
            }
            rs += __shfl_xor_sync(0xffffffffu, rs, 1);
            rs += __shfl_xor_sync(0xffffffffu, rs, 2);
            l_i[h] = l_i[h] * alpha + rs;
            m_i[h] = mnew;
            #pragma unroll
            for (int j = 0; j < 8; j++) { o[j][c0] *= alpha; o[j][c1] *= alpha; }
        }

        #pragma unroll
        for (int j = 0; j < 8; j++) {
            const int c   = j * 8 + 2 * t;
            const int cb  = c & ~3;
            const int rem = c & 3;
            *(float2*)&QPs[(mw + g)     * 64 + (cb ^ (g << 2)) + rem] =
                make_float2(f2tff(sc[j][0]), f2tff(sc[j][1]));
            *(float2*)&QPs[(mw + g + 8) * 64 + (cb ^ (g << 2)) + rem] =
                make_float2(f2tff(sc[j][2]), f2tff(sc[j][3]));
        }
        __syncwarp();

        cp_wait<1>();
        __syncthreads();

        #pragma unroll
        for (int ks = 0; ks < 8; ks++) {
            const int kk = ks * 8;
            unsigned a0, a1, a2, a3;
            ldsm4(a0, a1, a2, a3, QPs + (mw + arA) * 64 + ((kk + kaA) ^ xsw));
            const int koff = (kk + kbB) ^ xsw;
            #pragma unroll
            for (int j0 = 0; j0 < 8; j0 += 2) {
                unsigned b00, b10, b01, b11;
                ldsm4(b00, b10, b01, b11, Vs + (j0 * 8 + nrB) * 64 + koff);
                mma_tf32(o[j0],     a0, a1, a2, a3, b00, b10);
                mma_tf32(o[j0 + 1], a0, a1, a2, a3, b01, b11);
            }
        }
        __syncthreads();

        if (i + 1 < niter)
            ld_tile(Vs, vb + (kt + 1) * 64, TSEQ);
        CP_COMMIT();
    }

    float* po = g_po + rbase * HDIM;
    #pragma unroll
    for (int j = 0; j < 8; j++) {
        *(float2*)(po + (mw + g)     * HDIM + j * 8 + 2 * t) = make_float2(o[j][0], o[j][1]);
        *(float2*)(po + (mw + g + 8) * HDIM + j * 8 + 2 * t) = make_float2(o[j][2], o[j][3]);
    }
    if (t == 0) {
        g_pm[rbase + mw + g]     = m_i[0];
        g_pl[rbase + mw + g]     = l_i[0];
        g_pm[rbase + mw + g + 8] = m_i[1];
        g_pl[rbase + mw + g + 8] = l_i[1];
    }
}

// ---------------------------------------------------------------------------
// Kernel 3: combine 4 splits, 8 floats (2x float4) per thread.
// ---------------------------------------------------------------------------
__global__ __launch_bounds__(256) void attn_combine(float* __restrict__ out)
{
    int idx8 = blockIdx.x * 256 + threadIdx.x;
    int base = idx8 * 8;
    int r = base >> 6;

    float m[NSPLIT], l[NSPLIT];
    #pragma unroll
    for (int s = 0; s < NSPLIT; s++) {
        m[s] = g_pm[(size_t)s * BT_TOTAL + r];
        l[s] = g_pl[(size_t)s * BT_TOTAL + r];
    }
    float M = m[0];
    #pragma unroll
    for (int s = 1; s < NSPLIT; s++) M = fmaxf(M, m[s]);

    float wgt[NSPLIT], lsum = 0.0f;
    #pragma unroll
    for (int s = 0; s < NSPLIT; s++) {
        wgt[s] = exp2f(m[s] - M);
        lsum += l[s] * wgt[s];
    }
    float inv = 1.0f / lsum;

    float4 acc0 = make_float4(0.f, 0.f, 0.f, 0.f);
    float4 acc1 = make_float4(0.f, 0.f, 0.f, 0.f);
    #pragma unroll
    for (int s = 0; s < NSPLIT; s++) {
        const float* p = g_po + (size_t)s * BT_TOTAL * HDIM + base;
        float4 a0 = *(const float4*)(p);
        float4 a1 = *(const float4*)(p + 4);
        acc0.x += a0.x * wgt[s]; acc0.y += a0.y * wgt[s];
        acc0.z += a0.z * wgt[s]; acc0.w += a0.w * wgt[s];
        acc1.x += a1.x * wgt[s]; acc1.y += a1.y * wgt[s];
        acc1.z += a1.z * wgt[s]; acc1.w += a1.w * wgt[s];
    }
    float4 o0 = make_float4(acc0.x * inv, acc0.y * inv, acc0.z * inv, acc0.w * inv);
    float4 o1 = make_float4(acc1.x * inv, acc1.y * inv, acc1.z * inv, acc1.w * inv);
    *(float4*)(out + base)     = o0;
    *(float4*)(out + base + 4) = o1;
}

// ---------------------------------------------------------------------------
extern "C" void kernel_launch(void* const* d_in, const int* in_sizes, int n_in,
                              void* d_out, int out_size)
{
    (void)in_sizes; (void)n_in; (void)out_size;
    const float* x  = (const float*)d_in[0];
    const float* Wq = (const float*)d_in[1];
    const float* Wk = (const float*)d_in[2];
    const float* Wv = (const float*)d_in[3];
    float* out = (float*)d_out;

    const int proj_smem = (2 * XS_F + 3 * WS_F) * (int)sizeof(float);  // 92160
    cudaFuncSetAttribute(qkv_proj, cudaFuncAttributeMaxDynamicSharedMemorySize,
                         proj_smem);
    const int attn_smem = 4 * ATF * (int)sizeof(float);                // 65536
    cudaFuncSetAttribute(attn_part, cudaFuncAttributeMaxDynamicSharedMemorySize,
                         attn_smem);

    w_prep<<<(3 * HDIM * CDIM) / 256, 256>>>(Wq, Wk, Wv);

    qkv_proj<<<BT_TOTAL / 64, 256, proj_smem>>>(x);

    dim3 gattn(NSPLIT * TSEQ / 64, BATCH);
    attn_part<<<gattn, 128, attn_smem>>>(0);

    attn_combine<<<BT_TOTAL * HDIM / 2048, 256>>>(out);
}

// round 17
// speedup vs baseline: 1.2457x; 1.0766x over previous
#include <cuda_runtime.h>

#define BATCH 8
#define TSEQ 2048
#define CDIM 768
#define HDIM 64
#define BT_TOTAL (BATCH*TSEQ)
#define NSPLIT 2

// Projected Q, K (natural [b][s][h]) and V (TRANSPOSED [b][h][s]).
// All values already tf32-RNA-rounded; Q pre-scaled by 0.125*log2(e).
__device__ float g_q[BT_TOTAL*HDIM];
__device__ float g_k[BT_TOTAL*HDIM];
__device__ float g_v[BT_TOTAL*HDIM];
// split-K partials
__device__ float g_po[NSPLIT*BT_TOTAL*HDIM];
__device__ float g_pm[NSPLIT*BT_TOTAL];
__device__ float g_pl[NSPLIT*BT_TOTAL];
// W, pre-rounded (Wq pre-scaled), stored as per-chunk swizzled smem images
__device__ float g_wt[3*HDIM*CDIM];

// ---------------------------------------------------------------------------
__device__ __forceinline__ unsigned f2tf(float f) {
    unsigned u;
    asm("cvt.rna.tf32.f32 %0, %1;" : "=r"(u) : "f"(f));
    return u;
}
__device__ __forceinline__ float f2tff(float f) { return __uint_as_float(f2tf(f)); }

__device__ __forceinline__ void mma_tf32(float c[4],
                                         unsigned a0, unsigned a1, unsigned a2, unsigned a3,
                                         unsigned b0, unsigned b1) {
    asm volatile(
        "mma.sync.aligned.m16n8k8.row.col.f32.tf32.tf32.f32 "
        "{%0,%1,%2,%3},{%4,%5,%6,%7},{%8,%9},{%0,%1,%2,%3};"
        : "+f"(c[0]), "+f"(c[1]), "+f"(c[2]), "+f"(c[3])
        : "r"(a0), "r"(a1), "r"(a2), "r"(a3), "r"(b0), "r"(b1));
}

__device__ __forceinline__ void ldsm4(unsigned &r0, unsigned &r1, unsigned &r2, unsigned &r3,
                                      const float* p) {
    unsigned a = (unsigned)__cvta_generic_to_shared(p);
    asm volatile("ldmatrix.sync.aligned.m8n8.x4.shared.b16 {%0,%1,%2,%3}, [%4];"
                 : "=r"(r0), "=r"(r1), "=r"(r2), "=r"(r3) : "r"(a));
}

__device__ __forceinline__ void cpasync16(float* dst, const float* src) {
    unsigned a = (unsigned)__cvta_generic_to_shared(dst);
    asm volatile("cp.async.cg.shared.global [%0], [%1], 16;" :: "r"(a), "l"(src));
}
#define CP_COMMIT() asm volatile("cp.async.commit_group;")
template<int N> __device__ __forceinline__ void cp_wait() {
    asm volatile("cp.async.wait_group %0;" :: "n"(N));
}

// ---------------------------------------------------------------------------
// Kernel 0: W prep (unchanged).
// ---------------------------------------------------------------------------
__global__ __launch_bounds__(256) void w_prep(const float* __restrict__ Wq,
                                              const float* __restrict__ Wk,
                                              const float* __restrict__ Wv)
{
    int idx = blockIdx.x * 256 + threadIdx.x;        // over 768*192
    int k = idx / 192;
    int n = idx - k * 192;
    const float* W = (n < 64) ? Wq : (n < 128) ? Wk : Wv;
    float v = W[(size_t)k * HDIM + (n & 63)];
    if (n < 64) v *= 0.18033688011112042f;           // 0.125 * log2(e)
    int chunk = k >> 5;
    int kin = k & 31;
    int kg = kin >> 2, rem = kin & 3;
    g_wt[chunk * 6144 + n * 32 + ((kg * 4) ^ ((n & 7) << 2)) + rem] = f2tff(v);
}

// ---------------------------------------------------------------------------
// Kernel 1: FUSED QKV projection (unchanged from R13 pass).
// ---------------------------------------------------------------------------
#define XP 36
#define XS_F (64 * XP)
#define WS_F (192 * 32)

__global__ __launch_bounds__(256, 2) void qkv_proj(const float* __restrict__ x)
{
    extern __shared__ float psm[];
    float* Xst[2] = { psm, psm + XS_F };
    float* Wst[3] = { psm + 2*XS_F, psm + 2*XS_F + WS_F, psm + 2*XS_F + 2*WS_F };

    const int tid  = threadIdx.x;
    const int w    = tid >> 5;
    const int lane = tid & 31;
    const int wq   = w & 1;
    const int wn   = w >> 1;
    const int mw   = wq * 32;
    const int lrow = lane & 7;

    const int idxA = ((((lane >> 3) & 1) * 8 + lrow)) * XP + ((lane >> 4) & 1) * 4;
    const int nr   = ((lane >> 4) & 1) * 8 + lrow;
    const int kb   = ((lane >> 3) & 1) * 4;
    const int xrs  = lrow << 2;

    const size_t m0 = (size_t)blockIdx.x * 64;

    const int xr0 = tid >> 3,         xc0 = (tid & 7) * 4;
    const int xr1 = (tid + 256) >> 3, xc1 = (tid & 7) * 4;
    const int woff = tid * 4;

    float4 xg[2];

    auto ldg_x = [&](int kc) {
        xg[0] = *(const float4*)(x + (m0 + xr0) * CDIM + kc + xc0);
        xg[1] = *(const float4*)(x + (m0 + xr1) * CDIM + kc + xc1);
    };
    auto sts_x = [&](int s) {
        float4 v0 = xg[0], v1 = xg[1];
        v0.x = f2tff(v0.x); v0.y = f2tff(v0.y); v0.z = f2tff(v0.z); v0.w = f2tff(v0.w);
        v1.x = f2tff(v1.x); v1.y = f2tff(v1.y); v1.z = f2tff(v1.z); v1.w = f2tff(v1.w);
        *(float4*)&Xst[s][xr0 * XP + xc0] = v0;
        *(float4*)&Xst[s][xr1 * XP + xc1] = v1;
    };
    auto cp_w = [&](int ch, int s) {
        const float* src = g_wt + ch * WS_F + woff;
        float* dst = Wst[s] + woff;
        #pragma unroll
        for (int rep = 0; rep < 6; rep++)
            cpasync16(dst + rep * 1024, src + rep * 1024);
    };

    float acc[2][6][4];
    #pragma unroll
    for (int im = 0; im < 2; im++)
        #pragma unroll
        for (int j = 0; j < 6; j++)
            #pragma unroll
            for (int c = 0; c < 4; c++) acc[im][j][c] = 0.0f;

    cp_w(0, 0); CP_COMMIT();
    cp_w(1, 1); CP_COMMIT();
    ldg_x(0);
    sts_x(0);

    const int NCH = CDIM / 32;   // 24
    for (int ch = 0; ch < NCH; ch++) {
        const int sx = ch & 1;
        const int sw = ch % 3;
        if (ch + 1 < NCH) ldg_x((ch + 1) * 32);

        cp_wait<1>();
        __syncthreads();

        if (ch + 2 < NCH) cp_w(ch + 2, (ch + 2) % 3);
        CP_COMMIT();

        const float* Xs = Xst[sx];
        const float* Ws = Wst[sw];

        #pragma unroll
        for (int ks = 0; ks < 4; ks++) {
            const int kk = ks * 8;
            unsigned a00, a01, a02, a03, a10, a11, a12, a13;
            ldsm4(a00, a01, a02, a03, Xs + (mw)      * XP + kk + idxA);
            ldsm4(a10, a11, a12, a13, Xs + (mw + 16) * XP + kk + idxA);
            const int koff = (kk + kb) ^ xrs;
            #pragma unroll
            for (int j0 = 0; j0 < 6; j0 += 2) {
                unsigned b00, b10, b01, b11;
                ldsm4(b00, b10, b01, b11,
                      Ws + (wn * 48 + j0 * 8 + nr) * 32 + koff);
                mma_tf32(acc[0][j0],     a00, a01, a02, a03, b00, b10);
                mma_tf32(acc[0][j0 + 1], a00, a01, a02, a03, b01, b11);
                mma_tf32(acc[1][j0],     a10, a11, a12, a13, b00, b10);
                mma_tf32(acc[1][j0 + 1], a10, a11, a12, a13, b01, b11);
            }
        }
        if (ch + 1 < NCH) sts_x(sx ^ 1);
    }

    const int g = lane >> 2, t = lane & 3;
    const int bb = (int)(m0 >> 11);

    #pragma unroll
    for (int im = 0; im < 2; im++) {
        const size_t rb = m0 + mw + im * 16 + g;
        const int s0 = ((int)m0 & 2047) + mw + im * 16 + g;
        #pragma unroll
        for (int j = 0; j < 6; j++) {
            int n   = wn * 48 + j * 8;
            int mat = n >> 6;
            int col = (n & 63) + 2 * t;
            if (mat == 0) {
                *(float2*)(g_q + rb       * HDIM + col) =
                    make_float2(f2tff(acc[im][j][0]), f2tff(acc[im][j][1]));
                *(float2*)(g_q + (rb + 8) * HDIM + col) =
                    make_float2(f2tff(acc[im][j][2]), f2tff(acc[im][j][3]));
            } else if (mat == 1) {
                *(float2*)(g_k + rb       * HDIM + col) =
                    make_float2(f2tff(acc[im][j][0]), f2tff(acc[im][j][1]));
                *(float2*)(g_k + (rb + 8) * HDIM + col) =
                    make_float2(f2tff(acc[im][j][2]), f2tff(acc[im][j][3]));
            } else {
                g_v[((size_t)bb * 64 + col)     * TSEQ + s0]     = f2tff(acc[im][j][0]);
                g_v[((size_t)bb * 64 + col + 1) * TSEQ + s0]     = f2tff(acc[im][j][1]);
                g_v[((size_t)bb * 64 + col)     * TSEQ + s0 + 8] = f2tff(acc[im][j][2]);
                g_v[((size_t)bb * 64 + col + 1) * TSEQ + s0 + 8] = f2tff(acc[im][j][3]);
            }
        }
    }
}

// ---------------------------------------------------------------------------
// Kernel 2: split-K flash attention partials (R13 shape, 2 barriers/iter).
// q-tile 64, 4 warps x m16, 64KB smem, 3 CTAs/SM. Grid (64, 8).
// Pipeline: K double-buffered (wait<0> at a point where K(i) is the only
// pending group); V single-buffered, issued AFTER sync#1 (which post-dates
// every warp's O-GEMM(i-1)), committed BEFORE K(i+1) so wait<1> retires V(i)
// while K(i+1) stays in flight.
// ---------------------------------------------------------------------------
#define ATF 4096   // floats per 64x64 tile

__global__ __launch_bounds__(128, 3) void attn_part(int dummy)
{
    extern __shared__ float sm[];
    float* Vs  = sm + 2 * ATF;
    float* QPs = sm + 3 * ATF;

    const int tid  = threadIdx.x;
    const int w    = tid >> 5;
    const int lane = tid & 31;
    const int g    = lane >> 2;
    const int t    = lane & 3;
    const int b    = blockIdx.y;
    const int qt    = 31 - (blockIdx.x >> 1);
    const int split = blockIdx.x & 1;
    const int mw   = w * 16;
    const int lrow = lane & 7;

    const int nkv  = qt + 1;
    const int half = nkv >> 1;
    const int kt0  = split ? half : 0;
    const int kt1  = split ? nkv  : half;

    const size_t rbase = (size_t)split * BT_TOTAL + (size_t)b * TSEQ + qt * 64;

    if (kt0 == kt1) {
        for (int e = tid; e < 64 * HDIM; e += 128)
            g_po[(rbase + (e >> 6)) * HDIM + (e & 63)] = 0.0f;
        for (int r = tid; r < 64; r += 128) {
            g_pm[rbase + r] = -1e30f;
            g_pl[rbase + r] = 0.0f;
        }
        return;
    }

    const int arA = ((lane >> 3) & 1) * 8 + lrow;
    const int kaA = ((lane >> 4) & 1) * 4;
    const int nrB = ((lane >> 4) & 1) * 8 + lrow;
    const int kbB = ((lane >> 3) & 1) * 4;
    const int xsw = lrow << 2;

    const float* kb = g_k + (size_t)b * TSEQ * HDIM;
    const float* vb = g_v + (size_t)b * HDIM * TSEQ;

    auto ld_tile = [&](float* dst, const float* src, int pitch) {
        #pragma unroll
        for (int rep = 0; rep < 8; rep++) {
            int e = tid + rep * 128;
            int r = e >> 4, c4 = (e & 15) * 4;
            cpasync16(&dst[r * 64 + (c4 ^ ((r & 7) << 2))], src + r * pitch + c4);
        }
    };

    // prologue: Q, K(kt0) in flight; V comes inside iter 0.
    ld_tile(QPs, g_q + ((size_t)b * TSEQ + qt * 64) * HDIM, HDIM);
    CP_COMMIT();
    ld_tile(sm, kb + (size_t)kt0 * 64 * HDIM, HDIM);
    CP_COMMIT();
    cp_wait<1>();        // Q done; pending = [K(kt0)]
    __syncthreads();

    unsigned qa[8][4];
    #pragma unroll
    for (int ks = 0; ks < 8; ks++)
        ldsm4(qa[ks][0], qa[ks][1], qa[ks][2], qa[ks][3],
              QPs + (mw + arA) * 64 + ((ks * 8 + kaA) ^ xsw));

    float m_i[2] = {-1e30f, -1e30f};
    float l_i[2] = {0.0f, 0.0f};
    float o[8][4];
    #pragma unroll
    for (int j = 0; j < 8; j++)
        #pragma unroll
        for (int c = 0; c < 4; c++) o[j][c] = 0.0f;

    const int niter = kt1 - kt0;
    for (int i = 0; i < niter; i++) {
        const int kt = kt0 + i;
        const int s  = i & 1;

        cp_wait<0>();        // pending = [K(kt)] only -> K(kt) resident, no over-wait
        __syncthreads();     // sync#1: K visible; all warps past O-GEMM(i-1) -> Vs free

        // V(kt) first, then K(kt+1): commit order lets wait<1> retire V while K flies
        ld_tile(Vs, vb + kt * 64, TSEQ);
        CP_COMMIT();
        if (i + 1 < niter)
            ld_tile(sm + (s ^ 1) * ATF, kb + (size_t)(kt + 1) * 64 * HDIM, HDIM);
        CP_COMMIT();

        const float* Ks = sm + s * ATF;

        // ---- S = Q K^T ----
        float sc[8][4];
        #pragma unroll
        for (int j = 0; j < 8; j++)
            #pragma unroll
            for (int c = 0; c < 4; c++) sc[j][c] = 0.0f;

        #pragma unroll
        for (int ks = 0; ks < 8; ks++) {
            const int koff = (ks * 8 + kbB) ^ xsw;
            #pragma unroll
            for (int j0 = 0; j0 < 8; j0 += 2) {
                unsigned b00, b10, b01, b11;
                ldsm4(b00, b10, b01, b11, Ks + (j0 * 8 + nrB) * 64 + koff);
                mma_tf32(sc[j0],     qa[ks][0], qa[ks][1], qa[ks][2], qa[ks][3], b00, b10);
                mma_tf32(sc[j0 + 1], qa[ks][0], qa[ks][1], qa[ks][2], qa[ks][3], b01, b11);
            }
        }

        if (kt == qt) {
            #pragma unroll
            for (int j = 0; j < 8; j++)
                #pragma unroll
                for (int c = 0; c < 4; c++) {
                    int col = j * 8 + 2 * t + (c & 1);
                    int row = mw + g + ((c >> 1) << 3);
                    if (col > row) sc[j][c] = -1e30f;
                }
        }

        // ---- online softmax (exp2 domain) ----
        #pragma unroll
        for (int h = 0; h < 2; h++) {
            const int c0 = h * 2, c1 = h * 2 + 1;
            float mx = -1e30f;
            #pragma unroll
            for (int j = 0; j < 8; j++)
                mx = fmaxf(mx, fmaxf(sc[j][c0], sc[j][c1]));
            mx = fmaxf(mx, __shfl_xor_sync(0xffffffffu, mx, 1));
            mx = fmaxf(mx, __shfl_xor_sync(0xffffffffu, mx, 2));
            float mnew = fmaxf(m_i[h], mx);
            float alpha = exp2f(m_i[h] - mnew);
            float rs = 0.0f;
            #pragma unroll
            for (int j = 0; j < 8; j++) {
                sc[j][c0] = exp2f(sc[j][c0] - mnew);
                sc[j][c1] = exp2f(sc[j][c1] - mnew);
                rs += sc[j][c0] + sc[j][c1];
            }
            rs += __shfl_xor_sync(0xffffffffu, rs, 1);
            rs += __shfl_xor_sync(0xffffffffu, rs, 2);
            l_i[h] = l_i[h] * alpha + rs;
            m_i[h] = mnew;
            #pragma unroll
            for (int j = 0; j < 8; j++) { o[j][c0] *= alpha; o[j][c1] *= alpha; }
        }

        // ---- stage P (tf32-rounded) into this warp's rows of QPs ----
        #pragma unroll
        for (int j = 0; j < 8; j++) {
            const int c   = j * 8 + 2 * t;
            const int cb  = c & ~3;
            const int rem = c & 3;
            *(float2*)&QPs[(mw + g)     * 64 + (cb ^ (g << 2)) + rem] =
                make_float2(f2tff(sc[j][0]), f2tff(sc[j][1]));
            *(float2*)&QPs[(mw + g + 8) * 64 + (cb ^ (g << 2)) + rem] =
                make_float2(f2tff(sc[j][2]), f2tff(sc[j][3]));
        }
        __syncwarp();

        cp_wait<1>();        // pending [V(kt), K(kt+1)] -> V(kt) done, K may fly
        __syncthreads();     // sync#2: V visible to all warps

        // ---- O += P V ----
        #pragma unroll
        for (int ks = 0; ks < 8; ks++) {
            const int kk = ks * 8;
            unsigned a0, a1, a2, a3;
            ldsm4(a0, a1, a2, a3, QPs + (mw + arA) * 64 + ((kk + kaA) ^ xsw));
            const int koff = (kk + kbB) ^ xsw;
            #pragma unroll
            for (int j0 = 0; j0 < 8; j0 += 2) {
                unsigned b00, b10, b01, b11;
                ldsm4(b00, b10, b01, b11, Vs + (j0 * 8 + nrB) * 64 + koff);
                mma_tf32(o[j0],     a0, a1, a2, a3, b00, b10);
                mma_tf32(o[j0 + 1], a0, a1, a2, a3, b01, b11);
            }
        }
        // no sync#3: next iteration's sync#1 protects Vs overwrite
    }

    float* po = g_po + rbase * HDIM;
    #pragma unroll
    for (int j = 0; j < 8; j++) {
        *(float2*)(po + (mw + g)     * HDIM + j * 8 + 2 * t) = make_float2(o[j][0], o[j][1]);
        *(float2*)(po + (mw + g + 8) * HDIM + j * 8 + 2 * t) = make_float2(o[j][2], o[j][3]);
    }
    if (t == 0) {
        g_pm[rbase + mw + g]     = m_i[0];
        g_pl[rbase + mw + g]     = l_i[0];
        g_pm[rbase + mw + g + 8] = m_i[1];
        g_pl[rbase + mw + g + 8] = l_i[1];
    }
}

// ---------------------------------------------------------------------------
// Kernel 3: combine splits, 8 floats (2x float4) per thread (R13 version).
// ---------------------------------------------------------------------------
__global__ __launch_bounds__(256) void attn_combine(float* __restrict__ out)
{
    int idx8 = blockIdx.x * 256 + threadIdx.x;
    int base = idx8 * 8;
    int r = base >> 6;
    float m0 = g_pm[r], m1 = g_pm[BT_TOTAL + r];
    float l0 = g_pl[r], l1 = g_pl[BT_TOTAL + r];
    float4 a0 = *(const float4*)(g_po + base);
    float4 a1 = *(const float4*)(g_po + base + 4);
    float4 c0 = *(const float4*)(g_po + (size_t)BT_TOTAL * HDIM + base);
    float4 c1 = *(const float4*)(g_po + (size_t)BT_TOTAL * HDIM + base + 4);
    float M  = fmaxf(m0, m1);
    float w0 = exp2f(m0 - M), w1 = exp2f(m1 - M);
    float inv = 1.0f / (l0 * w0 + l1 * w1);
    float4 o0, o1;
    o0.x = (a0.x * w0 + c0.x * w1) * inv;
    o0.y = (a0.y * w0 + c0.y * w1) * inv;
    o0.z = (a0.z * w0 + c0.z * w1) * inv;
    o0.w = (a0.w * w0 + c0.w * w1) * inv;
    o1.x = (a1.x * w0 + c1.x * w1) * inv;
    o1.y = (a1.y * w0 + c1.y * w1) * inv;
    o1.z = (a1.z * w0 + c1.z * w1) * inv;
    o1.w = (a1.w * w0 + c1.w * w1) * inv;
    *(float4*)(out + base)     = o0;
    *(float4*)(out + base + 4) = o1;
}

// ---------------------------------------------------------------------------
extern "C" void kernel_launch(void* const* d_in, const int* in_sizes, int n_in,
                              void* d_out, int out_size)
{
    (void)in_sizes; (void)n_in; (void)out_size;
    const float* x  = (const float*)d_in[0];
    const float* Wq = (const float*)d_in[1];
    const float* Wk = (const float*)d_in[2];
    const float* Wv = (const float*)d_in[3];
    float* out = (float*)d_out;

    const int proj_smem = (2 * XS_F + 3 * WS_F) * (int)sizeof(float);  // 92160
    cudaFuncSetAttribute(qkv_proj, cudaFuncAttributeMaxDynamicSharedMemorySize,
                         proj_smem);
    const int attn_smem = 4 * ATF * (int)sizeof(float);                // 65536
    cudaFuncSetAttribute(attn_part, cudaFuncAttributeMaxDynamicSharedMemorySize,
                         attn_smem);

    w_prep<<<(3 * HDIM * CDIM) / 256, 256>>>(Wq, Wk, Wv);

    qkv_proj<<<BT_TOTAL / 64, 256, proj_smem>>>(x);

    dim3 gattn(2 * TSEQ / 64, BATCH);
    attn_part<<<gattn, 128, attn_smem>>>(0);

    attn_combine<<<BT_TOTAL * HDIM / 2048, 256>>>(out);
}